// round 2
// baseline (speedup 1.0000x reference)
#include <cuda_runtime.h>
#include <cuda_bf16.h>
#include <cstdint>
#include <cstddef>

// Fixed problem dims
#define TOK 8192
#define CDIM 1024
#define HDIM 4096

#define BM 128
#define BN 128
#define BK 32

// Scratch (static device globals: allowed; no allocations)
__device__ float          g_h[(size_t)TOK * HDIM];     // 128 MiB fp32 hidden
__device__ __nv_bfloat16  g_xq[(size_t)TOK * CDIM];    // quantized x codes
__device__ __nv_bfloat16  g_hq[(size_t)TOK * HDIM];    // quantized h codes
__device__ __nv_bfloat16  g_wq1[(size_t)HDIM * CDIM];  // W1 codes, [N][K]
__device__ __nv_bfloat16  g_wq2[(size_t)CDIM * HDIM];  // W2 codes, [N][K]
__device__ float          g_dsw1[HDIM];
__device__ float          g_dsw2[CDIM];
__device__ unsigned       g_xmax_bits;
__device__ unsigned       g_hmax_bits;

__device__ __forceinline__ float clampq(float v) {
    return fminf(fmaxf(v, -127.f), 127.f);
}

// ---------------------------------------------------------------------------
__global__ void k_init() { g_xmax_bits = 0u; g_hmax_bits = 0u; }

// ---------------------------------------------------------------------------
// max |x * mask| over the whole tensor (vectorized, exact)
__global__ void k_absmax_x(const float4* __restrict__ x4,
                           const float* __restrict__ mask,
                           int n4, int c4) {
    float lm = 0.f;
    for (int i = blockIdx.x * blockDim.x + threadIdx.x; i < n4;
         i += gridDim.x * blockDim.x) {
        float m = fabsf(mask[i / c4]);
        float4 v = x4[i];
        float a = fmaxf(fmaxf(fabsf(v.x), fabsf(v.y)),
                        fmaxf(fabsf(v.z), fabsf(v.w)));
        lm = fmaxf(lm, a * m);
    }
    #pragma unroll
    for (int o = 16; o; o >>= 1) lm = fmaxf(lm, __shfl_xor_sync(0xffffffffu, lm, o));
    __shared__ float red[8];
    if ((threadIdx.x & 31) == 0) red[threadIdx.x >> 5] = lm;
    __syncthreads();
    if (threadIdx.x == 0) {
        float m = red[0];
        #pragma unroll
        for (int r = 1; r < 8; r++) m = fmaxf(m, red[r]);
        atomicMax(&g_xmax_bits, __float_as_uint(m));
    }
}

// ---------------------------------------------------------------------------
// quantize x -> bf16 integer codes
__global__ void k_quant_x(const float4* __restrict__ x4, int n4) {
    float sx = 127.f / fmaxf(__uint_as_float(g_xmax_bits), 1e-6f);
    for (int i = blockIdx.x * blockDim.x + threadIdx.x; i < n4;
         i += gridDim.x * blockDim.x) {
        float4 v = x4[i];
        __nv_bfloat16 t[4];
        t[0] = __float2bfloat16(clampq(rintf(v.x * sx)));
        t[1] = __float2bfloat16(clampq(rintf(v.y * sx)));
        t[2] = __float2bfloat16(clampq(rintf(v.z * sx)));
        t[3] = __float2bfloat16(clampq(rintf(v.w * sx)));
        reinterpret_cast<uint2*>(g_xq)[i] = *reinterpret_cast<uint2*>(t);
    }
}

// quantize h -> bf16 integer codes
__global__ void k_quant_h(int n4) {
    float sh = 127.f / fmaxf(__uint_as_float(g_hmax_bits), 1e-6f);
    const float4* h4 = reinterpret_cast<const float4*>(g_h);
    for (int i = blockIdx.x * blockDim.x + threadIdx.x; i < n4;
         i += gridDim.x * blockDim.x) {
        float4 v = h4[i];
        __nv_bfloat16 t[4];
        t[0] = __float2bfloat16(clampq(rintf(v.x * sh)));
        t[1] = __float2bfloat16(clampq(rintf(v.y * sh)));
        t[2] = __float2bfloat16(clampq(rintf(v.z * sh)));
        t[3] = __float2bfloat16(clampq(rintf(v.w * sh)));
        reinterpret_cast<uint2*>(g_hq)[i] = *reinterpret_cast<uint2*>(t);
    }
}

// ---------------------------------------------------------------------------
// per-output-column weight max + quantize + transpose to [N][K]
__global__ void k_quant_w(const float* __restrict__ W, int K, int N, int which) {
    __nv_bfloat16* wq = which ? g_wq2 : g_wq1;
    float* dsw = which ? g_dsw2 : g_dsw1;
    int n0 = blockIdx.x * 32;
    int tn = threadIdx.x & 31, kg = threadIdx.x >> 5;

    float mx = 0.f;
    for (int k = kg; k < K; k += 8)
        mx = fmaxf(mx, fabsf(W[(size_t)k * N + n0 + tn]));
    __shared__ float sm[8][32];
    sm[kg][tn] = mx;
    __syncthreads();
    if (kg == 0) {
        float v = sm[0][tn];
        #pragma unroll
        for (int r = 1; r < 8; r++) v = fmaxf(v, sm[r][tn]);
        float swv = 127.f / fmaxf(v, 1e-6f);
        dsw[n0 + tn] = 1.f / swv;
        sm[0][tn] = swv;
    }
    __syncthreads();

    int nl = threadIdx.x >> 3, ks = threadIdx.x & 7;
    float swv = sm[0][nl];
    int n = n0 + nl;
    int chunk = K >> 3;
    for (int j = 0; j < chunk; j += 8) {
        int k = ks * chunk + j;
        __nv_bfloat16 t[8];
        #pragma unroll
        for (int r = 0; r < 8; r++)
            t[r] = __float2bfloat16(clampq(rintf(W[(size_t)(k + r) * N + n] * swv)));
        *reinterpret_cast<uint4*>(wq + (size_t)n * K + k) =
            *reinterpret_cast<const uint4*>(t);
    }
}

// ---------------------------------------------------------------------------
__device__ __forceinline__ void mma16816(float* d, const uint32_t* a, const uint32_t* b) {
    asm volatile(
        "mma.sync.aligned.m16n8k16.row.col.f32.bf16.bf16.f32 "
        "{%0,%1,%2,%3}, {%4,%5,%6,%7}, {%8,%9}, {%0,%1,%2,%3};\n"
        : "+f"(d[0]), "+f"(d[1]), "+f"(d[2]), "+f"(d[3])
        : "r"(a[0]), "r"(a[1]), "r"(a[2]), "r"(a[3]), "r"(b[0]), "r"(b[1]));
}

// XOR-swizzled smem tile access ([rows][32] bf16, 16B-chunk swizzle by (row>>1)&3)
__device__ __forceinline__ uint32_t lds_pair(const __nv_bfloat16* S, int row, int col) {
    int word = col >> 1;
    int wp = (((word >> 2) ^ ((row >> 1) & 3)) << 2) | (word & 3);
    return *reinterpret_cast<const uint32_t*>(S + row * BK + wp * 2);
}

// GEMM: D[M,N] = A[M,K] (codes) x B[N,K]^T (codes), dequant epilogue.
// FIRST: out = relu(acc*dsA*dsw[n] + bias[n]) -> g_h, fused |h*m| max.
// else : out = acc*dsA*dsw[n] + bias[n]       -> out_param.
template <bool FIRST>
__global__ void __launch_bounds__(256)
k_gemm(const float* __restrict__ bias, const float* __restrict__ mask,
       float* __restrict__ out_param, int M, int N, int K) {
    const __nv_bfloat16* A = FIRST ? g_xq : g_hq;
    const __nv_bfloat16* B = FIRST ? g_wq1 : g_wq2;
    const float* dsw = FIRST ? g_dsw1 : g_dsw2;
    float amax = __uint_as_float(FIRST ? g_xmax_bits : g_hmax_bits);
    float sA = 127.f / fmaxf(amax, 1e-6f);
    float dsA = 1.f / sA;

    __shared__ __align__(16) __nv_bfloat16 As[2][BM * BK];
    __shared__ __align__(16) __nv_bfloat16 Bs[2][BN * BK];

    int t = threadIdx.x, lane = t & 31, w = t >> 5;
    int m0 = blockIdx.y * BM, n0 = blockIdx.x * BN;
    int wm = w & 3, wn = w >> 2;              // 4 x 2 warp grid
    int mbase = wm * 32, nbase = wn * 64;

    float acc[2][8][4];
    #pragma unroll
    for (int a = 0; a < 2; a++)
        #pragma unroll
        for (int b = 0; b < 8; b++)
            #pragma unroll
            for (int c = 0; c < 4; c++) acc[a][b][c] = 0.f;

    auto ldg_tile = [&](const __nv_bfloat16* P, int r0, int k0, uint4* v) {
        #pragma unroll
        for (int i = 0; i < 2; i++) {
            int u = t + i * 256, row = u >> 2, c4 = u & 3;
            v[i] = *reinterpret_cast<const uint4*>(
                P + (size_t)(r0 + row) * K + k0 + c4 * 8);
        }
    };
    auto sts_tile = [&](__nv_bfloat16* S, const uint4* v) {
        #pragma unroll
        for (int i = 0; i < 2; i++) {
            int u = t + i * 256, row = u >> 2, c4 = u & 3;
            int c4s = c4 ^ ((row >> 1) & 3);
            *reinterpret_cast<uint4*>(S + row * BK + c4s * 8) = v[i];
        }
    };

    uint4 va[2], vb[2];
    ldg_tile(A, m0, 0, va);
    ldg_tile(B, n0, 0, vb);
    sts_tile(As[0], va);
    sts_tile(Bs[0], vb);
    __syncthreads();

    int buf = 0;
    for (int kt = 0; kt < K; kt += BK) {
        bool nxt = (kt + BK) < K;
        if (nxt) { ldg_tile(A, m0, kt + BK, va); ldg_tile(B, n0, kt + BK, vb); }
        #pragma unroll
        for (int ks = 0; ks < BK; ks += 16) {
            uint32_t af[2][4], bfr[8][2];
            #pragma unroll
            for (int mt = 0; mt < 2; mt++) {
                int r = mbase + mt * 16 + (lane >> 2);
                int c = ks + (lane & 3) * 2;
                af[mt][0] = lds_pair(As[buf], r, c);
                af[mt][1] = lds_pair(As[buf], r + 8, c);
                af[mt][2] = lds_pair(As[buf], r, c + 8);
                af[mt][3] = lds_pair(As[buf], r + 8, c + 8);
            }
            #pragma unroll
            for (int nt = 0; nt < 8; nt++) {
                int r = nbase + nt * 8 + (lane >> 2);
                int c = ks + (lane & 3) * 2;
                bfr[nt][0] = lds_pair(Bs[buf], r, c);
                bfr[nt][1] = lds_pair(Bs[buf], r, c + 8);
            }
            #pragma unroll
            for (int mt = 0; mt < 2; mt++)
                #pragma unroll
                for (int nt = 0; nt < 8; nt++)
                    mma16816(acc[mt][nt], af[mt], bfr[nt]);
        }
        if (nxt) { sts_tile(As[buf ^ 1], va); sts_tile(Bs[buf ^ 1], vb); }
        __syncthreads();
        buf ^= 1;
    }

    // Epilogue: dequant + bias (+relu + fused h-max)
    float lmax = 0.f;
    #pragma unroll
    for (int mt = 0; mt < 2; mt++) {
        #pragma unroll
        for (int nt = 0; nt < 8; nt++) {
            int gcol = n0 + nbase + nt * 8 + (lane & 3) * 2;
            float ds0 = dsA * dsw[gcol], ds1 = dsA * dsw[gcol + 1];
            float bb0 = bias[gcol], bb1 = bias[gcol + 1];
            #pragma unroll
            for (int half = 0; half < 2; half++) {
                int grow = m0 + mbase + mt * 16 + (lane >> 2) + half * 8;
                float v0 = acc[mt][nt][half * 2 + 0] * ds0 + bb0;
                float v1 = acc[mt][nt][half * 2 + 1] * ds1 + bb1;
                if (FIRST) {
                    v0 = fmaxf(v0, 0.f);
                    v1 = fmaxf(v1, 0.f);
                    float mk = fabsf(mask[grow]);
                    lmax = fmaxf(lmax, fmaxf(v0, v1) * mk);
                    float2 st = make_float2(v0, v1);
                    *reinterpret_cast<float2*>(&g_h[(size_t)grow * N + gcol]) = st;
                } else {
                    float2 st = make_float2(v0, v1);
                    *reinterpret_cast<float2*>(&out_param[(size_t)grow * N + gcol]) = st;
                }
            }
        }
    }
    if (FIRST) {
        #pragma unroll
        for (int o = 16; o; o >>= 1)
            lmax = fmaxf(lmax, __shfl_xor_sync(0xffffffffu, lmax, o));
        __shared__ float red[8];
        if (lane == 0) red[w] = lmax;
        __syncthreads();
        if (t == 0) {
            float m = red[0];
            #pragma unroll
            for (int r = 1; r < 8; r++) m = fmaxf(m, red[r]);
            atomicMax(&g_hmax_bits, __float_as_uint(m));
        }
    }
}

// ---------------------------------------------------------------------------
extern "C" void kernel_launch(void* const* d_in, const int* in_sizes, int n_in,
                              void* d_out, int out_size) {
    const float* x    = (const float*)d_in[0];
    const float* mask = (const float*)d_in[1];
    const float* W1   = (const float*)d_in[2];
    const float* b1   = (const float*)d_in[3];
    const float* W2   = (const float*)d_in[4];
    const float* b2   = (const float*)d_in[5];
    float* out = (float*)d_out;

    int M = in_sizes[1];            // 8192 tokens
    int C = in_sizes[0] / M;        // 1024
    int H = in_sizes[3];            // 4096

    k_init<<<1, 1>>>();
    k_absmax_x<<<1024, 256>>>((const float4*)x, mask, (M * C) / 4, C / 4);
    k_quant_x<<<1024, 256>>>((const float4*)x, (M * C) / 4);
    k_quant_w<<<H / 32, 256>>>(W1, C, H, 0);
    k_quant_w<<<C / 32, 256>>>(W2, H, C, 1);

    dim3 g1(H / BN, M / BM);
    k_gemm<true><<<g1, 256>>>(b1, mask, nullptr, M, H, C);

    k_quant_h<<<2048, 256>>>((M * H) / 4);

    dim3 g2(C / BN, M / BM);
    k_gemm<false><<<g2, 256>>>(b2, mask, out, M, C, H);
}